// round 2
// baseline (speedup 1.0000x reference)
#include <cuda_runtime.h>
#include <cuda_bf16.h>
#include <math.h>

#define NN      50000   // nodes
#define FF      128     // features
#define EE      600000  // edges (before self loops)
#define EP      (EE + NN)
#define NID     5000
#define HEADS   8
// dh = 16, scale = 1/sqrt(16) = 0.25

// ---------------- device scratch (static; no allocations) ----------------
__device__ float g_Q[NN * FF];
__device__ float g_K[NN * FF];
__device__ float g_V[NN * FF];
__device__ int   g_deg[NN];
__device__ int   g_offs[NN + 1];
__device__ int   g_cursor[NN];
__device__ int   g_scol[EP];

// ---------------- zero degree histogram ----------------
__global__ void zero_deg_kernel() {
    int i = blockIdx.x * blockDim.x + threadIdx.x;
    if (i < NN) g_deg[i] = 0;
}

// ---------------- fused QKV GEMM: out = (relu?)(x @ W + b) ----------------
// blockIdx.y selects which matrix: 0->Q(relu), 1->K(relu), 2->V(no relu,no bias)
#define BM 128
#define BN 128
#define BK 8
__global__ __launch_bounds__(256, 2) void gemm3_kernel(
    const float* __restrict__ x,
    const float* __restrict__ Wq, const float* __restrict__ bq,
    const float* __restrict__ Wk, const float* __restrict__ bk,
    const float* __restrict__ Wv)
{
    const int which = blockIdx.y;
    const float* W = (which == 0) ? Wq : (which == 1) ? Wk : Wv;
    const float* bias = (which == 0) ? bq : (which == 1) ? bk : nullptr;
    float* out = (which == 0) ? g_Q : (which == 1) ? g_K : g_V;

    __shared__ float As[BK][BM + 4];   // padded, transposed A tile
    __shared__ float Bs[BK][BN];

    const int tid = threadIdx.x;            // 0..255
    const int tx = tid & 15;                // col group
    const int ty = tid >> 4;                // row group
    const int rowBase = blockIdx.x * BM;

    // A tile load mapping: 128 rows x 8 cols = 256 float4
    const int aRow = tid >> 1;
    const int aCol = (tid & 1) * 4;
    // B tile load mapping: 8 rows x 128 cols = 256 float4
    const int bRow = tid >> 5;
    const int bCol = (tid & 31) * 4;

    float acc[8][8];
#pragma unroll
    for (int i = 0; i < 8; i++)
#pragma unroll
        for (int j = 0; j < 8; j++) acc[i][j] = 0.f;

    for (int kc = 0; kc < FF; kc += BK) {
        // load A (x) tile, transposed into smem
        float4 av = make_float4(0.f, 0.f, 0.f, 0.f);
        int gRow = rowBase + aRow;
        if (gRow < NN)
            av = *reinterpret_cast<const float4*>(&x[(size_t)gRow * FF + kc + aCol]);
        As[aCol + 0][aRow] = av.x;
        As[aCol + 1][aRow] = av.y;
        As[aCol + 2][aRow] = av.z;
        As[aCol + 3][aRow] = av.w;
        // load B (W) tile
        float4 bv = *reinterpret_cast<const float4*>(&W[(size_t)(kc + bRow) * 128 + bCol]);
        *reinterpret_cast<float4*>(&Bs[bRow][bCol]) = bv;
        __syncthreads();

#pragma unroll
        for (int k = 0; k < BK; k++) {
            float ar[8], br[8];
            *reinterpret_cast<float4*>(&ar[0]) = *reinterpret_cast<float4*>(&As[k][ty * 8]);
            *reinterpret_cast<float4*>(&ar[4]) = *reinterpret_cast<float4*>(&As[k][ty * 8 + 4]);
            *reinterpret_cast<float4*>(&br[0]) = *reinterpret_cast<float4*>(&Bs[k][tx * 8]);
            *reinterpret_cast<float4*>(&br[4]) = *reinterpret_cast<float4*>(&Bs[k][tx * 8 + 4]);
#pragma unroll
            for (int i = 0; i < 8; i++)
#pragma unroll
                for (int j = 0; j < 8; j++)
                    acc[i][j] = fmaf(ar[i], br[j], acc[i][j]);
        }
        __syncthreads();
    }

    // epilogue
    float bvreg[8];
#pragma unroll
    for (int j = 0; j < 8; j++) bvreg[j] = (which < 2) ? bias[tx * 8 + j] : 0.f;

#pragma unroll
    for (int i = 0; i < 8; i++) {
        int r = rowBase + ty * 8 + i;
        if (r < NN) {
            float vals[8];
#pragma unroll
            for (int j = 0; j < 8; j++) {
                float v = acc[i][j] + bvreg[j];
                if (which < 2) v = fmaxf(v, 0.f);
                vals[j] = v;
            }
            *reinterpret_cast<float4*>(&out[(size_t)r * FF + tx * 8]) =
                *reinterpret_cast<float4*>(&vals[0]);
            *reinterpret_cast<float4*>(&out[(size_t)r * FF + tx * 8 + 4]) =
                *reinterpret_cast<float4*>(&vals[4]);
        }
    }
}

// ---------------- id scatter GEMM: V[id] += x[id] @ kernel_id ----------------
__global__ void idgemm_kernel(const float* __restrict__ x,
                              const int* __restrict__ id_index,
                              const float* __restrict__ Wid)
{
    const int i = blockIdx.x;       // 0..NID-1
    const int j = threadIdx.x;      // 0..127
    const int r = id_index[i];
    __shared__ float xs[FF];
    xs[j] = x[(size_t)r * FF + j];
    __syncthreads();
    float s = 0.f;
#pragma unroll 8
    for (int k = 0; k < FF; k++)
        s = fmaf(xs[k], Wid[k * 128 + j], s);
    atomicAdd(&g_V[(size_t)r * FF + j], s);
}

// ---------------- histogram of destination (row) degrees ----------------
__global__ void hist_kernel(const int* __restrict__ ei) {
    int e = blockIdx.x * blockDim.x + threadIdx.x;
    if (e < EP) {
        int row = (e < EE) ? ei[e] : (e - EE);
        atomicAdd(&g_deg[row], 1);
    }
}

// ---------------- single-block exclusive scan over degrees ----------------
__global__ void scan_kernel() {
    __shared__ int part[1024];
    const int t = threadIdx.x;
    const int CH = (NN + 1023) / 1024;   // 49
    const int base = t * CH;
    int s = 0;
    for (int i = 0; i < CH; i++) {
        int idx = base + i;
        if (idx < NN) s += g_deg[idx];
    }
    part[t] = s;
    __syncthreads();
    // inclusive Hillis-Steele scan
    for (int off = 1; off < 1024; off <<= 1) {
        int v = (t >= off) ? part[t - off] : 0;
        __syncthreads();
        part[t] += v;
        __syncthreads();
    }
    int run = (t == 0) ? 0 : part[t - 1];
    for (int i = 0; i < CH; i++) {
        int idx = base + i;
        if (idx < NN) {
            g_offs[idx] = run;
            g_cursor[idx] = run;
            run += g_deg[idx];
        }
    }
    if (t == 1023) g_offs[NN] = run;
}

// ---------------- scatter edges into destination-sorted order ----------------
__global__ void scatter_kernel(const int* __restrict__ ei) {
    int e = blockIdx.x * blockDim.x + threadIdx.x;
    if (e < EP) {
        int row, col;
        if (e < EE) { row = ei[e]; col = ei[EE + e]; }
        else        { row = e - EE; col = row; }
        int pos = atomicAdd(&g_cursor[row], 1);
        g_scol[pos] = col;
    }
}

// ---------------- per-node attention aggregation (one warp per node) -------
__global__ __launch_bounds__(256) void aggregate_kernel(
    const float* __restrict__ bias, float* __restrict__ out)
{
    const int gwarp = (blockIdx.x * blockDim.x + threadIdx.x) >> 5;
    const int lane = threadIdx.x & 31;
    if (gwarp >= NN) return;
    const int n = gwarp;

    // lane holds columns [4*lane, 4*lane+4); head = lane/4 (dh=16 = 4 lanes)
    const float4 q = *reinterpret_cast<const float4*>(&g_Q[(size_t)n * FF + lane * 4]);
    float4 acc = make_float4(0.f, 0.f, 0.f, 0.f);
    float denom = 0.f;

    const int s = g_offs[n];
    const int e = g_offs[n + 1];
    for (int p = s; p < e; p++) {
        const int col = g_scol[p];
        const float4 kv = *reinterpret_cast<const float4*>(&g_K[(size_t)col * FF + lane * 4]);
        float d = q.x * kv.x + q.y * kv.y + q.z * kv.z + q.w * kv.w;
        // reduce the 16-dim head dot across the 4 lanes of the head group
        d += __shfl_xor_sync(0xffffffff, d, 1);
        d += __shfl_xor_sync(0xffffffff, d, 2);
        const float w = __expf(d * 0.25f);   // 1/sqrt(dh), dh=16; no max needed (bounded logits)
        const float4 vv = *reinterpret_cast<const float4*>(&g_V[(size_t)col * FF + lane * 4]);
        acc.x = fmaf(w, vv.x, acc.x);
        acc.y = fmaf(w, vv.y, acc.y);
        acc.z = fmaf(w, vv.z, acc.z);
        acc.w = fmaf(w, vv.w, acc.w);
        denom += w;
    }
    const float inv = 1.f / denom;   // >= 1 edge guaranteed (self loop)
    const float4 b = *reinterpret_cast<const float4*>(&bias[lane * 4]);
    float4 o;
    o.x = fmaf(acc.x, inv, b.x);
    o.y = fmaf(acc.y, inv, b.y);
    o.z = fmaf(acc.z, inv, b.z);
    o.w = fmaf(acc.w, inv, b.w);
    *reinterpret_cast<float4*>(&out[(size_t)n * FF + lane * 4]) = o;
}

// ---------------- launch ----------------
extern "C" void kernel_launch(void* const* d_in, const int* in_sizes, int n_in,
                              void* d_out, int out_size)
{
    const float* x    = (const float*)d_in[0];
    const int*   ei   = (const int*)d_in[1];     // JAX x64 disabled -> int32
    const int*   idix = (const int*)d_in[2];     // int32
    const float* Wq   = (const float*)d_in[3];
    const float* bq   = (const float*)d_in[4];
    const float* Wk   = (const float*)d_in[5];
    const float* bk   = (const float*)d_in[6];
    const float* Wv   = (const float*)d_in[7];
    const float* Wid  = (const float*)d_in[8];
    const float* bo   = (const float*)d_in[9];
    float* out = (float*)d_out;

    // 1) reset histogram
    zero_deg_kernel<<<(NN + 255) / 256, 256>>>();

    // 2) Q/K/V GEMMs
    dim3 ggrid((NN + BM - 1) / BM, 3);
    gemm3_kernel<<<ggrid, 256>>>(x, Wq, bq, Wk, bk, Wv);

    // 3) id scatter-add GEMM into V
    idgemm_kernel<<<NID, 128>>>(x, idix, Wid);

    // 4) counting sort of edges by destination
    hist_kernel<<<(EP + 255) / 256, 256>>>(ei);
    scan_kernel<<<1, 1024>>>();
    scatter_kernel<<<(EP + 255) / 256, 256>>>(ei);

    // 5) fused attention softmax + aggregation, one warp per node
    aggregate_kernel<<<(NN * 32 + 255) / 256, 256>>>(bo, out);
}

// round 3
// speedup vs baseline: 1.3538x; 1.3538x over previous
#include <cuda_runtime.h>
#include <cuda_fp16.h>
#include <math.h>

#define NN      50000   // nodes
#define FF      128     // features
#define EE      600000  // edges (before self loops)
#define EP      (EE + NN)
#define NID     5000
// dh = 16, scale = 0.25

// ---------------- device scratch (static; no allocations) ----------------
__device__ __half g_Qh[NN * FF];
__device__ __half g_Kh[NN * FF];
__device__ __half g_Vh[NN * FF];
__device__ int    g_deg[NN];
__device__ int    g_offs[NN + 1];
__device__ int    g_cursor[NN];
__device__ int    g_scol[EP];

// ---------------- helpers ----------------
__device__ __forceinline__ unsigned f2tf(float f) {
    unsigned r;
    asm("cvt.rna.tf32.f32 %0, %1;" : "=r"(r) : "f"(f));
    return r;
}

__device__ __forceinline__ void mma_tf32(float* c, const unsigned* a, const unsigned* b) {
    asm volatile(
        "mma.sync.aligned.m16n8k8.row.col.f32.tf32.tf32.f32 "
        "{%0,%1,%2,%3},{%4,%5,%6,%7},{%8,%9},{%0,%1,%2,%3};"
        : "+f"(c[0]), "+f"(c[1]), "+f"(c[2]), "+f"(c[3])
        : "r"(a[0]), "r"(a[1]), "r"(a[2]), "r"(a[3]), "r"(b[0]), "r"(b[1]));
}

// ---------------- zero degree histogram ----------------
__global__ void zero_deg_kernel() {
    int i = blockIdx.x * blockDim.x + threadIdx.x;
    if (i < NN) g_deg[i] = 0;
}

// ---------------- tf32 QKV GEMM: out_h = (relu?)(x @ W + b) ----------------
// blockIdx.y: 0->Q(relu+bias), 1->K(relu+bias), 2->V(plain)
// Block tile 128x128, 8 warps (4m x 2n), warp tile 32x64, mma m16n8k8.
#define AS_STRIDE 20
#define BS_STRIDE 136
#define GEMM_SMEM ((128 * AS_STRIDE + 128 * BS_STRIDE) * 4)

__global__ __launch_bounds__(256, 2) void gemm3_kernel(
    const float* __restrict__ x,
    const float* __restrict__ Wq, const float* __restrict__ bq,
    const float* __restrict__ Wk, const float* __restrict__ bk,
    const float* __restrict__ Wv)
{
    const int which = blockIdx.y;
    const float* W    = (which == 0) ? Wq : (which == 1) ? Wk : Wv;
    const float* bias = (which == 0) ? bq : (which == 1) ? bk : nullptr;
    __half* out = (which == 0) ? g_Qh : (which == 1) ? g_Kh : g_Vh;

    extern __shared__ unsigned smem[];
    unsigned* As = smem;                     // [128][20]  (16 k-cols used)
    unsigned* Bs = smem + 128 * AS_STRIDE;   // [128][136]

    const int tid  = threadIdx.x;
    const int lane = tid & 31;
    const int warp = tid >> 5;
    const int wm   = warp >> 1;              // 0..3
    const int wn   = warp & 1;               // 0..1
    const int rowBase = blockIdx.x * 128;

    // ---- load full W (128x128) into Bs, converted to tf32 ----
    for (int i = tid * 4; i < FF * FF; i += 256 * 4) {
        int r = i >> 7, c = i & 127;
        float4 v = *reinterpret_cast<const float4*>(&W[i]);
        Bs[r * BS_STRIDE + c + 0] = f2tf(v.x);
        Bs[r * BS_STRIDE + c + 1] = f2tf(v.y);
        Bs[r * BS_STRIDE + c + 2] = f2tf(v.z);
        Bs[r * BS_STRIDE + c + 3] = f2tf(v.w);
    }

    float acc[2][8][4];
#pragma unroll
    for (int i = 0; i < 2; i++)
#pragma unroll
        for (int j = 0; j < 8; j++)
#pragma unroll
            for (int t = 0; t < 4; t++) acc[i][j][t] = 0.f;

    const int lq = lane >> 2;   // groupID
    const int lr = lane & 3;    // thread in group

    for (int kc = 0; kc < FF; kc += 16) {
        // ---- load A chunk 128 x 16 ----
#pragma unroll
        for (int t = 0; t < 2; t++) {
            int j = tid + t * 256;          // float4 index, 0..511
            int r = j >> 2;
            int c4 = (j & 3) * 4;
            int gRow = rowBase + r;
            float4 v = make_float4(0.f, 0.f, 0.f, 0.f);
            if (gRow < NN)
                v = *reinterpret_cast<const float4*>(&x[(size_t)gRow * FF + kc + c4]);
            As[r * AS_STRIDE + c4 + 0] = f2tf(v.x);
            As[r * AS_STRIDE + c4 + 1] = f2tf(v.y);
            As[r * AS_STRIDE + c4 + 2] = f2tf(v.z);
            As[r * AS_STRIDE + c4 + 3] = f2tf(v.w);
        }
        __syncthreads();

#pragma unroll
        for (int kk = 0; kk < 2; kk++) {
            const int kb = kk * 8 + lr;
            unsigned bf[8][2];
#pragma unroll
            for (int j = 0; j < 8; j++) {
                int n = wn * 64 + j * 8 + lq;
                bf[j][0] = Bs[(kc + kb) * BS_STRIDE + n];
                bf[j][1] = Bs[(kc + kb + 4) * BS_STRIDE + n];
            }
            unsigned af[2][4];
#pragma unroll
            for (int i = 0; i < 2; i++) {
                int r0 = wm * 32 + i * 16 + lq;
                af[i][0] = As[r0 * AS_STRIDE + kk * 8 + lr];
                af[i][1] = As[(r0 + 8) * AS_STRIDE + kk * 8 + lr];
                af[i][2] = As[r0 * AS_STRIDE + kk * 8 + lr + 4];
                af[i][3] = As[(r0 + 8) * AS_STRIDE + kk * 8 + lr + 4];
            }
#pragma unroll
            for (int i = 0; i < 2; i++)
#pragma unroll
                for (int j = 0; j < 8; j++)
                    mma_tf32(acc[i][j], af[i], bf[j]);
        }
        __syncthreads();
    }

    // ---- epilogue: bias (+relu) -> half2 store ----
#pragma unroll
    for (int i = 0; i < 2; i++) {
#pragma unroll
        for (int j = 0; j < 8; j++) {
            int c = wn * 64 + j * 8 + lr * 2;
            float b0 = 0.f, b1 = 0.f;
            if (which < 2) { b0 = bias[c]; b1 = bias[c + 1]; }
            int r0 = rowBase + wm * 32 + i * 16 + lq;
            int r1 = r0 + 8;
            float v00 = acc[i][j][0] + b0, v01 = acc[i][j][1] + b1;
            float v10 = acc[i][j][2] + b0, v11 = acc[i][j][3] + b1;
            if (which < 2) {
                v00 = fmaxf(v00, 0.f); v01 = fmaxf(v01, 0.f);
                v10 = fmaxf(v10, 0.f); v11 = fmaxf(v11, 0.f);
            }
            if (r0 < NN)
                *reinterpret_cast<__half2*>(&out[(size_t)r0 * FF + c]) =
                    __floats2half2_rn(v00, v01);
            if (r1 < NN)
                *reinterpret_cast<__half2*>(&out[(size_t)r1 * FF + c]) =
                    __floats2half2_rn(v10, v11);
        }
    }
}

// -------- id scatter GEMM: V[id] += x[id] @ kernel_id (half2 atomics) --------
__global__ void idgemm_kernel(const float* __restrict__ x,
                              const int* __restrict__ id_index,
                              const float* __restrict__ Wid)
{
    const int i = blockIdx.x;       // 0..NID-1
    const int t = threadIdx.x;      // 0..63 (2 cols each)
    const int r = id_index[i];
    __shared__ float xs[FF];
    xs[t] = x[(size_t)r * FF + t];
    xs[t + 64] = x[(size_t)r * FF + t + 64];
    __syncthreads();
    float s0 = 0.f, s1 = 0.f;
#pragma unroll 8
    for (int k = 0; k < FF; k++) {
        float2 w = *reinterpret_cast<const float2*>(&Wid[k * FF + 2 * t]);
        s0 = fmaf(xs[k], w.x, s0);
        s1 = fmaf(xs[k], w.y, s1);
    }
    atomicAdd(reinterpret_cast<__half2*>(&g_Vh[(size_t)r * FF + 2 * t]),
              __floats2half2_rn(s0, s1));
}

// ---------------- histogram of destination (row) degrees ----------------
__global__ void hist_kernel(const int* __restrict__ ei) {
    int e = blockIdx.x * blockDim.x + threadIdx.x;
    if (e < EP) {
        int row = (e < EE) ? ei[e] : (e - EE);
        atomicAdd(&g_deg[row], 1);
    }
}

// ---------------- single-block exclusive scan over degrees ----------------
__global__ void scan_kernel() {
    __shared__ int part[1024];
    const int t = threadIdx.x;
    const int CH = (NN + 1023) / 1024;
    const int base = t * CH;
    int s = 0;
    for (int i = 0; i < CH; i++) {
        int idx = base + i;
        if (idx < NN) s += g_deg[idx];
    }
    part[t] = s;
    __syncthreads();
    for (int off = 1; off < 1024; off <<= 1) {
        int v = (t >= off) ? part[t - off] : 0;
        __syncthreads();
        part[t] += v;
        __syncthreads();
    }
    int run = (t == 0) ? 0 : part[t - 1];
    for (int i = 0; i < CH; i++) {
        int idx = base + i;
        if (idx < NN) {
            g_offs[idx] = run;
            g_cursor[idx] = run;
            run += g_deg[idx];
        }
    }
    if (t == 1023) g_offs[NN] = run;
}

// ---------------- scatter edges into destination-sorted order ----------------
__global__ void scatter_kernel(const int* __restrict__ ei) {
    int e = blockIdx.x * blockDim.x + threadIdx.x;
    if (e < EP) {
        int row, col;
        if (e < EE) { row = ei[e]; col = ei[EE + e]; }
        else        { row = e - EE; col = row; }
        int pos = atomicAdd(&g_cursor[row], 1);
        g_scol[pos] = col;
    }
}

// -------- per-node attention aggregation (one warp per node, fp16 gathers) ---
__global__ __launch_bounds__(256) void aggregate_kernel(
    const float* __restrict__ bias, float* __restrict__ out)
{
    const int n = (blockIdx.x * blockDim.x + threadIdx.x) >> 5;
    const int lane = threadIdx.x & 31;
    if (n >= NN) return;

    // lane holds cols [4*lane, 4*lane+4); head = lane/4 (dh=16 = 4 lanes)
    uint2 qu = *reinterpret_cast<const uint2*>(&g_Qh[(size_t)n * FF + lane * 4]);
    const float2 q0 = __half22float2(*reinterpret_cast<__half2*>(&qu.x));
    const float2 q1 = __half22float2(*reinterpret_cast<__half2*>(&qu.y));

    float a0 = 0.f, a1 = 0.f, a2 = 0.f, a3 = 0.f;
    float denom = 0.f;

    const int s = g_offs[n];
    const int e = g_offs[n + 1];
    int p = s;

    // 2x unrolled edge loop for MLP
    for (; p + 2 <= e; p += 2) {
        const int c0 = g_scol[p];
        const int c1 = g_scol[p + 1];
        uint2 k0 = *reinterpret_cast<const uint2*>(&g_Kh[(size_t)c0 * FF + lane * 4]);
        uint2 k1 = *reinterpret_cast<const uint2*>(&g_Kh[(size_t)c1 * FF + lane * 4]);
        uint2 v0 = *reinterpret_cast<const uint2*>(&g_Vh[(size_t)c0 * FF + lane * 4]);
        uint2 v1 = *reinterpret_cast<const uint2*>(&g_Vh[(size_t)c1 * FF + lane * 4]);

        float2 ka = __half22float2(*reinterpret_cast<__half2*>(&k0.x));
        float2 kb = __half22float2(*reinterpret_cast<__half2*>(&k0.y));
        float d0 = q0.x * ka.x + q0.y * ka.y + q1.x * kb.x + q1.y * kb.y;
        ka = __half22float2(*reinterpret_cast<__half2*>(&k1.x));
        kb = __half22float2(*reinterpret_cast<__half2*>(&k1.y));
        float d1 = q0.x * ka.x + q0.y * ka.y + q1.x * kb.x + q1.y * kb.y;

        d0 += __shfl_xor_sync(0xffffffff, d0, 1);
        d1 += __shfl_xor_sync(0xffffffff, d1, 1);
        d0 += __shfl_xor_sync(0xffffffff, d0, 2);
        d1 += __shfl_xor_sync(0xffffffff, d1, 2);

        const float w0 = __expf(d0 * 0.25f);
        const float w1 = __expf(d1 * 0.25f);

        float2 va = __half22float2(*reinterpret_cast<__half2*>(&v0.x));
        float2 vb = __half22float2(*reinterpret_cast<__half2*>(&v0.y));
        a0 = fmaf(w0, va.x, a0); a1 = fmaf(w0, va.y, a1);
        a2 = fmaf(w0, vb.x, a2); a3 = fmaf(w0, vb.y, a3);
        va = __half22float2(*reinterpret_cast<__half2*>(&v1.x));
        vb = __half22float2(*reinterpret_cast<__half2*>(&v1.y));
        a0 = fmaf(w1, va.x, a0); a1 = fmaf(w1, va.y, a1);
        a2 = fmaf(w1, vb.x, a2); a3 = fmaf(w1, vb.y, a3);
        denom += w0 + w1;
    }
    for (; p < e; p++) {
        const int c0 = g_scol[p];
        uint2 k0 = *reinterpret_cast<const uint2*>(&g_Kh[(size_t)c0 * FF + lane * 4]);
        float2 ka = __half22float2(*reinterpret_cast<__half2*>(&k0.x));
        float2 kb = __half22float2(*reinterpret_cast<__half2*>(&k0.y));
        float d0 = q0.x * ka.x + q0.y * ka.y + q1.x * kb.x + q1.y * kb.y;
        d0 += __shfl_xor_sync(0xffffffff, d0, 1);
        d0 += __shfl_xor_sync(0xffffffff, d0, 2);
        const float w0 = __expf(d0 * 0.25f);
        uint2 v0 = *reinterpret_cast<const uint2*>(&g_Vh[(size_t)c0 * FF + lane * 4]);
        float2 va = __half22float2(*reinterpret_cast<__half2*>(&v0.x));
        float2 vb = __half22float2(*reinterpret_cast<__half2*>(&v0.y));
        a0 = fmaf(w0, va.x, a0); a1 = fmaf(w0, va.y, a1);
        a2 = fmaf(w0, vb.x, a2); a3 = fmaf(w0, vb.y, a3);
        denom += w0;
    }

    const float inv = 1.f / denom;   // >= 1 edge guaranteed (self loop)
    const float4 b = *reinterpret_cast<const float4*>(&bias[lane * 4]);
    float4 o;
    o.x = fmaf(a0, inv, b.x);
    o.y = fmaf(a1, inv, b.y);
    o.z = fmaf(a2, inv, b.z);
    o.w = fmaf(a3, inv, b.w);
    *reinterpret_cast<float4*>(&out[(size_t)n * FF + lane * 4]) = o;
}

// ---------------- launch ----------------
extern "C" void kernel_launch(void* const* d_in, const int* in_sizes, int n_in,
                              void* d_out, int out_size)
{
    const float* x    = (const float*)d_in[0];
    const int*   ei   = (const int*)d_in[1];     // JAX x64 disabled -> int32
    const int*   idix = (const int*)d_in[2];
    const float* Wq   = (const float*)d_in[3];
    const float* bq   = (const float*)d_in[4];
    const float* Wk   = (const float*)d_in[5];
    const float* bk   = (const float*)d_in[6];
    const float* Wv   = (const float*)d_in[7];
    const float* Wid  = (const float*)d_in[8];
    const float* bo   = (const float*)d_in[9];
    float* out = (float*)d_out;

    static bool attr_done = false;
    if (!attr_done) {
        cudaFuncSetAttribute(gemm3_kernel,
                             cudaFuncAttributeMaxDynamicSharedMemorySize, GEMM_SMEM);
        attr_done = true;
    }

    // 1) reset histogram
    zero_deg_kernel<<<(NN + 255) / 256, 256>>>();

    // 2) Q/K/V GEMMs (tf32 tensor cores, fp16 outputs)
    dim3 ggrid((NN + 127) / 128, 3);
    gemm3_kernel<<<ggrid, 256, GEMM_SMEM>>>(x, Wq, bq, Wk, bk, Wv);

    // 3) id scatter-add GEMM into V (half2 atomics)
    idgemm_kernel<<<NID, 64>>>(x, idix, Wid);

    // 4) counting sort of edges by destination
    hist_kernel<<<(EP + 255) / 256, 256>>>(ei);
    scan_kernel<<<1, 1024>>>();
    scatter_kernel<<<(EP + 255) / 256, 256>>>(ei);

    // 5) fused attention softmax + aggregation, one warp per node
    aggregate_kernel<<<(NN * 32 + 255) / 256, 256>>>(bo, out);
}